// round 16
// baseline (speedup 1.0000x reference)
#include <cuda_runtime.h>
#include <cstdint>

// IndexAddInplace as a GATHER: out[j] = x[j] + sum_{i: idx[i]==j} src[i]
// x: [N_DST=100000, D=512] f32, idx: [N_SRC=200000] int64/int32 (detected),
// src: [N_SRC, D] f32.
//
// build : SPLIT per-row metadata: primary int4 {cnt, s0, s1, s2} (16B,
//         covers 86% of rows) + extension int4 {s3..s6} read only when
//         cnt > 3 (~14% of rows). >7 sources spill to an i+1-encoded linked
//         list (0 = end => zero-init is the empty state). 2 idx elements
//         per thread (vector loads).
// gather: one WARP per row, 256-thr blocks. One unconditional 16B meta load
//         (single L2 round trip on the common path). 4 independent x
//         LDG.128s + 4*m src LDG.128s, streaming + L2::256B prefetch.
//         Self-cleans cnt behind __syncwarp() — graph replays need no init.
// Traffic floor: 205MB x-read + 410MB src-read + 205MB out-write (+~2MB index).
// Gather measured at 7.04 TB/s (~88% of achievable mixed-R/W HBM) — the wall.

#define MAX_DST 100000
#define MAX_SRC 200000
#define K_PRI   3            // slots in the primary 16B record
#define K_SLOTS 7            // total inline slots (primary + extension)
#define DETECT_WORDS 512     // odd-word sample for dtype detection

__device__ int4 g_meta[MAX_DST];             // {cnt, s0, s1, s2}; zero-init = empty
__device__ int4 g_ext[MAX_DST];              // {s3, s4, s5, s6}
__device__ int  g_head[MAX_DST];             // stores i+1; 0 = end (zero-init OK)
__device__ int  g_next[MAX_SRC];             // stores i+1 links

// Streaming 128-bit load with L2 256B prefetch hint (evict-first policy).
__device__ __forceinline__ float4 ldcs_pf(const float4* p) {
    float4 v;
    asm volatile("ld.global.cs.L2::256B.v4.f32 {%0,%1,%2,%3}, [%4];"
                 : "=f"(v.x), "=f"(v.y), "=f"(v.z), "=f"(v.w)
                 : "l"(p));
    return v;
}

__device__ __forceinline__ void insert(int d, int i) {
    int pos = atomicAdd(&((int*)&g_meta[d])[0], 1);
    if (pos < K_PRI)         ((int*)&g_meta[d])[1 + pos] = i;
    else if (pos < K_SLOTS)  ((int*)&g_ext[d])[pos - K_PRI] = i;
    else                     g_next[i] = atomicExch(&g_head[d], i + 1);
}

// ---- 1. build inverted index: 2 elements per thread, vector idx loads ----
// Per-block dtype detect: int64 idx with values < 2^31 has ALL odd 32-bit
// words == 0 (LE); int32 idx has random dst indices there (P(all 0) ~ 0).
__global__ void build_kernel(const void* __restrict__ idx_raw, int n_src) {
    const int* idx32 = (const int*)idx_raw;
    int local = 0;
    #pragma unroll
    for (int k = 0; k < DETECT_WORDS / 256; k++) {
        int w = threadIdx.x + k * 256;
        if (2 * w + 1 < n_src) local |= idx32[2 * w + 1];
    }
    const int is64 = !__syncthreads_or(local != 0);

    int t = blockIdx.x * blockDim.x + threadIdx.x;
    int i0 = t * 2;
    if (i0 >= n_src) return;
    const bool has1 = (i0 + 1) < n_src;

    int d0, d1 = 0;
    if (is64) {
        if (has1) {
            longlong2 p = ((const longlong2*)idx_raw)[t];
            d0 = (int)p.x; d1 = (int)p.y;
        } else {
            d0 = (int)((const long long*)idx_raw)[i0];
        }
    } else {
        if (has1) {
            int2 p = ((const int2*)idx_raw)[t];
            d0 = p.x; d1 = p.y;
        } else {
            d0 = idx32[i0];
        }
    }

    insert(d0, i0);
    if (has1) insert(d1, i0 + 1);
}

// ---- 2. gather: one WARP per row; lane handles cols c, c+32, c+64, c+96 ----
__global__ void __launch_bounds__(256)
gather_kernel(const float4* __restrict__ x,
              const float4* __restrict__ src,
              float4* __restrict__ out,
              int dv, int n_dst) {
    const int warp_id = (blockIdx.x * blockDim.x + threadIdx.x) >> 5;
    if (warp_id >= n_dst) return;
    const int j = warp_id;
    const int lane = threadIdx.x & 31;

    // Primary record: one unconditional 16B load (86% of rows need nothing
    // more — single L2 round trip before src addresses resolve).
    const int4 a = __ldg(&g_meta[j]);
    const int n = a.x;
    const int m = n < K_SLOTS ? n : K_SLOTS;

    const size_t rbase = (size_t)j * dv + lane;  // dv = 128, 4 chunks of 32

    float4 acc[4];
    #pragma unroll
    for (int q = 0; q < 4; q++)
        acc[q] = ldcs_pf(&x[rbase + q * 32]);    // independent streaming loads

    int ids[K_SLOTS];
    ids[0] = a.y; ids[1] = a.z; ids[2] = a.w;
    if (n > K_PRI) {                             // ~14% of rows
        const int4 b = __ldg(&g_ext[j]);
        ids[3] = b.x; ids[4] = b.y; ids[5] = b.z; ids[6] = b.w;
    }

    #pragma unroll
    for (int k = 0; k < K_SLOTS; k++) {
        if (k < m) {
            const size_t sbase = (size_t)ids[k] * dv + lane;
            #pragma unroll
            for (int q = 0; q < 4; q++) {
                float4 v = ldcs_pf(&src[sbase + q * 32]);
                acc[q].x += v.x; acc[q].y += v.y;
                acc[q].z += v.z; acc[q].w += v.w;
            }
        }
    }

    // Rare spill (>7 sources, ~0.1% of rows): walk the i+1-encoded chain.
    if (n > K_SLOTS) {
        for (int v1 = __ldg(&g_head[j]); v1 != 0; v1 = __ldg(&g_next[v1 - 1])) {
            const size_t sbase = (size_t)(v1 - 1) * dv + lane;
            #pragma unroll
            for (int q = 0; q < 4; q++) {
                float4 v = ldcs_pf(&src[sbase + q * 32]);
                acc[q].x += v.x; acc[q].y += v.y;
                acc[q].z += v.z; acc[q].w += v.w;
            }
        }
    }

    #pragma unroll
    for (int q = 0; q < 4; q++)
        __stcs(&out[rbase + q * 32], acc[q]);

    // Whole warp has consumed this row's state before lane 0 resets it.
    __syncwarp();
    if (lane == 0) {
        ((int*)&g_meta[j])[0] = 0;               // cnt = 0 (slots gated by cnt)
        if (n > K_SLOTS) g_head[j] = 0;
    }
}

extern "C" void kernel_launch(void* const* d_in, const int* in_sizes, int n_in,
                              void* d_out, int out_size) {
    // Inputs: x [N_DST*D] f32, idx [N_SRC], src [N_SRC*D] f32
    const float* x   = (const float*)d_in[0];
    const void*  idx = (const void*)d_in[1];
    const float* src = (const float*)d_in[2];
    float* out = (float*)d_out;

    const int n_src = in_sizes[1];             // 200000
    const int d     = in_sizes[2] / n_src;     // 512
    const int n_dst = out_size / d;            // 100000
    const int dv    = d / 4;                   // 128 float4/row

    const int n_pairs = (n_src + 1) / 2;
    build_kernel<<<(n_pairs + 255) / 256, 256>>>(idx, n_src);

    const int rows_per_block = 256 / 32;       // 8 warps = 8 rows
    gather_kernel<<<(n_dst + rows_per_block - 1) / rows_per_block, 256>>>(
        (const float4*)x, (const float4*)src, (float4*)out, dv, n_dst);
}

// round 17
// speedup vs baseline: 1.0338x; 1.0338x over previous
#include <cuda_runtime.h>
#include <cstdint>

// IndexAddInplace as a GATHER: out[j] = x[j] + sum_{i: idx[i]==j} src[i]
// x: [N_DST=100000, D=512] f32, idx: [N_SRC=200000] int64/int32 (detected),
// src: [N_SRC, D] f32.
//
// FINAL (best-measured configuration, R13 = 125.06us; session 220.8 -> 125.1,
// gather at 7.04 TB/s on the 823 MB algorithmic traffic floor = ~88% of
// achievable mixed-R/W HBM3e — at the memory wall).
//
// build : PACKED per-row metadata meta[j] = {cnt, slot0..slot6} (32B).
//         atomicAdd on word 0; slots inline; >7 sources spill to an
//         i+1-encoded linked list (0 = end => zero-init is the empty state).
//         2 idx elements per thread (vector loads).
// gather: one WARP per row, 256-thr blocks. Row metadata in TWO UNCONDITIONAL
//         int4 loads — single L2 round trip, no cnt->slot dependency (R16
//         proved conditional meta splitting regresses: heavy rows carry ~40%
//         of src loads and a serialized second round trip stalls them).
//         4 independent x LDG.128s + 4*m src LDG.128s, streaming + L2::256B
//         prefetch. Self-cleans cnt behind __syncwarp() so graph replays
//         need no init kernel.
// Traffic floor: 205MB x-read + 410MB src-read + 205MB out-write (+~5MB index).

#define MAX_DST 100000
#define MAX_SRC 200000
#define K_SLOTS 7            // slots per packed 32B record (word 0 = cnt)
#define DETECT_WORDS 512     // odd-word sample for dtype detection

__device__ int4 g_meta[MAX_DST * 2];         // zero-init => cnt = 0 (empty)
__device__ int  g_head[MAX_DST];             // stores i+1; 0 = end (zero-init OK)
__device__ int  g_next[MAX_SRC];             // stores i+1 links

// Streaming 128-bit load with L2 256B prefetch hint (evict-first policy).
__device__ __forceinline__ float4 ldcs_pf(const float4* p) {
    float4 v;
    asm volatile("ld.global.cs.L2::256B.v4.f32 {%0,%1,%2,%3}, [%4];"
                 : "=f"(v.x), "=f"(v.y), "=f"(v.z), "=f"(v.w)
                 : "l"(p));
    return v;
}

__device__ __forceinline__ void insert(int d, int i) {
    int* rec = (int*)&g_meta[d * 2];         // {cnt, slot0..slot6}
    int pos = atomicAdd(rec, 1);
    if (pos < K_SLOTS) rec[1 + pos] = i;
    else               g_next[i] = atomicExch(&g_head[d], i + 1);
}

// ---- 1. build inverted index: 2 elements per thread, vector idx loads ----
// Per-block dtype detect: int64 idx with values < 2^31 has ALL odd 32-bit
// words == 0 (LE); int32 idx has random dst indices there (P(all 0) ~ 0).
__global__ void build_kernel(const void* __restrict__ idx_raw, int n_src) {
    const int* idx32 = (const int*)idx_raw;
    int local = 0;
    #pragma unroll
    for (int k = 0; k < DETECT_WORDS / 256; k++) {
        int w = threadIdx.x + k * 256;
        if (2 * w + 1 < n_src) local |= idx32[2 * w + 1];
    }
    const int is64 = !__syncthreads_or(local != 0);

    int t = blockIdx.x * blockDim.x + threadIdx.x;
    int i0 = t * 2;
    if (i0 >= n_src) return;
    const bool has1 = (i0 + 1) < n_src;

    int d0, d1 = 0;
    if (is64) {
        if (has1) {
            longlong2 p = ((const longlong2*)idx_raw)[t];
            d0 = (int)p.x; d1 = (int)p.y;
        } else {
            d0 = (int)((const long long*)idx_raw)[i0];
        }
    } else {
        if (has1) {
            int2 p = ((const int2*)idx_raw)[t];
            d0 = p.x; d1 = p.y;
        } else {
            d0 = idx32[i0];
        }
    }

    insert(d0, i0);
    if (has1) insert(d1, i0 + 1);
}

// ---- 2. gather: one WARP per row; lane handles cols c, c+32, c+64, c+96 ----
__global__ void __launch_bounds__(256)
gather_kernel(const float4* __restrict__ x,
              const float4* __restrict__ src,
              float4* __restrict__ out,
              int dv, int n_dst) {
    const int warp_id = (blockIdx.x * blockDim.x + threadIdx.x) >> 5;
    if (warp_id >= n_dst) return;
    const int j = warp_id;
    const int lane = threadIdx.x & 31;

    // Whole row record in two unconditional 16B loads — one L2 round trip.
    const int4 a = __ldg(&g_meta[j * 2]);
    const int4 b = __ldg(&g_meta[j * 2 + 1]);
    const int n = a.x;
    const int m = n < K_SLOTS ? n : K_SLOTS;
    const int ids[K_SLOTS] = { a.y, a.z, a.w, b.x, b.y, b.z, b.w };

    const size_t rbase = (size_t)j * dv + lane;  // dv = 128, 4 chunks of 32

    float4 acc[4];
    #pragma unroll
    for (int q = 0; q < 4; q++)
        acc[q] = ldcs_pf(&x[rbase + q * 32]);    // independent streaming loads

    #pragma unroll
    for (int k = 0; k < K_SLOTS; k++) {
        if (k < m) {
            const size_t sbase = (size_t)ids[k] * dv + lane;
            #pragma unroll
            for (int q = 0; q < 4; q++) {
                float4 v = ldcs_pf(&src[sbase + q * 32]);
                acc[q].x += v.x; acc[q].y += v.y;
                acc[q].z += v.z; acc[q].w += v.w;
            }
        }
    }

    // Rare spill (>7 sources, ~0.1% of rows): walk the i+1-encoded chain.
    if (n > K_SLOTS) {
        for (int v1 = __ldg(&g_head[j]); v1 != 0; v1 = __ldg(&g_next[v1 - 1])) {
            const size_t sbase = (size_t)(v1 - 1) * dv + lane;
            #pragma unroll
            for (int q = 0; q < 4; q++) {
                float4 v = ldcs_pf(&src[sbase + q * 32]);
                acc[q].x += v.x; acc[q].y += v.y;
                acc[q].z += v.z; acc[q].w += v.w;
            }
        }
    }

    #pragma unroll
    for (int q = 0; q < 4; q++)
        __stcs(&out[rbase + q * 32], acc[q]);

    // Whole warp has consumed this row's state before lane 0 resets it.
    __syncwarp();
    if (lane == 0) {
        ((int*)&g_meta[j * 2])[0] = 0;           // cnt = 0 (slots gated by cnt)
        if (n > K_SLOTS) g_head[j] = 0;
    }
}

extern "C" void kernel_launch(void* const* d_in, const int* in_sizes, int n_in,
                              void* d_out, int out_size) {
    // Inputs: x [N_DST*D] f32, idx [N_SRC], src [N_SRC*D] f32
    const float* x   = (const float*)d_in[0];
    const void*  idx = (const void*)d_in[1];
    const float* src = (const float*)d_in[2];
    float* out = (float*)d_out;

    const int n_src = in_sizes[1];             // 200000
    const int d     = in_sizes[2] / n_src;     // 512
    const int n_dst = out_size / d;            // 100000
    const int dv    = d / 4;                   // 128 float4/row

    const int n_pairs = (n_src + 1) / 2;
    build_kernel<<<(n_pairs + 255) / 256, 256>>>(idx, n_src);

    const int rows_per_block = 256 / 32;       // 8 warps = 8 rows
    gather_kernel<<<(n_dst + rows_per_block - 1) / rows_per_block, 256>>>(
        (const float4*)x, (const float4*)src, (float4*)out, dv, n_dst);
}